// round 3
// baseline (speedup 1.0000x reference)
#include <cuda_runtime.h>
#include <math.h>

#define SS 32
#define EE 64
#define VV 32000
#define BB 4096
#define SB (SS*BB)

__device__ float g_Gf[(size_t)SB*256];
__device__ float g_Gb[(size_t)SB*256];
__device__ float g_hf[(size_t)SB*EE];
__device__ float g_hb[(size_t)SB*EE];
__device__ float g_Gc[(size_t)SB*512];
__device__ float g_hL[BB*128];

__device__ __forceinline__ float sigm(float x){ return 1.0f/(1.0f+__expf(-x)); }

// ---------- K1: input gates (fwd/bwd): G = emb[x] @ WihT + bih + bhh ----------
__global__ __launch_bounds__(256) void k1(const void* __restrict__ xraw,
    const float* __restrict__ emb,
    const float* __restrict__ Wf, const float* __restrict__ bif, const float* __restrict__ bhf,
    const float* __restrict__ Wb, const float* __restrict__ bib, const float* __restrict__ bhb)
{
    extern __shared__ float sm[];
    float* Wsh = sm;            // [64][268]
    float* Ash = sm + 64*268;   // [32][64]
    __shared__ int s64;
    const int tx = threadIdx.x, dir = blockIdx.y;
    const float* W = dir ? Wb : Wf;
    const float* bi = dir ? bib : bif;
    const float* bh = dir ? bhb : bhf;
    float* G = dir ? g_Gb : g_Gf;
    for (int idx = tx; idx < 256*64; idx += 256)
        Wsh[(idx&63)*268 + (idx>>6)] = W[idx];
    if (tx == 0) {
        const int* p = (const int*)xraw; int f = 1;
        for (int q = 0; q < 64; q++) if (p[2*q+1] != 0) { f = 0; break; }
        s64 = f;
    }
    __syncthreads();
    const int r0blk = blockIdx.x*32;
    {
        const long long* x64 = (const long long*)xraw;
        const int* x32 = (const int*)xraw;
        const int is64 = s64;
        for (int idx = tx; idx < 32*64; idx += 256) {
            int r = idx>>6, k = idx&63, rr = r0blk + r, pos;
            if (dir) { int t = rr>>12, b = rr&4095; pos = (SS-1-t)*BB + b; }
            else pos = rr;
            int tok = is64 ? (int)x64[pos] : x32[pos];
            Ash[idx] = emb[tok*EE + k];
        }
    }
    __syncthreads();
    const int c0 = (tx&63)*4, r0 = (tx>>6)*8;
    float acc[8][4];
    #pragma unroll
    for (int j = 0; j < 4; j++) { float bv = bi[c0+j]+bh[c0+j];
        #pragma unroll
        for (int i = 0; i < 8; i++) acc[i][j] = bv; }
    #pragma unroll 4
    for (int k0 = 0; k0 < 64; k0 += 4) {
        float4 a[8];
        #pragma unroll
        for (int i = 0; i < 8; i++) a[i] = *(const float4*)&Ash[(r0+i)*64 + k0];
        #pragma unroll
        for (int kk = 0; kk < 4; kk++) {
            float4 w = *(const float4*)&Wsh[(k0+kk)*268 + c0];
            #pragma unroll
            for (int i = 0; i < 8; i++) {
                float av = kk==0?a[i].x:kk==1?a[i].y:kk==2?a[i].z:a[i].w;
                acc[i][0]+=av*w.x; acc[i][1]+=av*w.y; acc[i][2]+=av*w.z; acc[i][3]+=av*w.w;
            }
        }
    }
    #pragma unroll
    for (int i = 0; i < 8; i++)
        *(float4*)&G[(size_t)(r0blk+r0+i)*256 + c0] =
            make_float4(acc[i][0],acc[i][1],acc[i][2],acc[i][3]);
}

// ---------- K2: fwd/bwd recurrence, persistent per 16 batch rows ----------
__global__ __launch_bounds__(256) void k2(
    const float* __restrict__ Whf, const float* __restrict__ h0f, const float* __restrict__ c0f,
    const float* __restrict__ Whb, const float* __restrict__ h0b, const float* __restrict__ c0b)
{
    extern __shared__ float sm[];
    float* Wsh = sm;              // [64][268]
    float* gsh = sm + 64*268;     // [16][256]
    float* hsh = gsh + 16*256;    // [16][64]
    const int tx = threadIdx.x, dir = blockIdx.y;
    const float* Whh = dir ? Whb : Whf;
    const float* h0 = dir ? h0b : h0f;
    const float* c0 = dir ? c0b : c0f;
    const float* G = dir ? g_Gb : g_Gf;
    float* H = dir ? g_hb : g_hf;
    const int b0 = blockIdx.x*16;
    for (int idx = tx; idx < 256*64; idx += 256)
        Wsh[(idx&63)*268 + (idx>>6)] = Whh[idx];
    for (int idx = tx; idx < 16*64; idx += 256)
        hsh[idx] = h0[(b0 + (idx>>6))*64 + (idx&63)];
    float creg[4];
    #pragma unroll
    for (int ii = 0; ii < 4; ii++) {
        int it = tx + 256*ii;
        creg[ii] = c0[(b0 + (it>>6))*64 + (it&63)];
    }
    __syncthreads();
    const int c0i = (tx&63)*4, r0 = (tx>>6)*4, gate = c0i>>6;
    for (int t = 0; t < SS; t++) {
        float acc[4][4];
        #pragma unroll
        for (int i = 0; i < 4; i++) {
            float4 g4 = *(const float4*)&G[(size_t)(t*BB + b0 + r0 + i)*256 + c0i];
            acc[i][0]=g4.x; acc[i][1]=g4.y; acc[i][2]=g4.z; acc[i][3]=g4.w;
        }
        #pragma unroll 4
        for (int k0 = 0; k0 < 64; k0 += 4) {
            float4 a[4];
            #pragma unroll
            for (int i = 0; i < 4; i++) a[i] = *(const float4*)&hsh[(r0+i)*64 + k0];
            #pragma unroll
            for (int kk = 0; kk < 4; kk++) {
                float4 w = *(const float4*)&Wsh[(k0+kk)*268 + c0i];
                #pragma unroll
                for (int i = 0; i < 4; i++) {
                    float av = kk==0?a[i].x:kk==1?a[i].y:kk==2?a[i].z:a[i].w;
                    acc[i][0]+=av*w.x; acc[i][1]+=av*w.y; acc[i][2]+=av*w.z; acc[i][3]+=av*w.w;
                }
            }
        }
        #pragma unroll
        for (int i = 0; i < 4; i++)
            #pragma unroll
            for (int j = 0; j < 4; j++) {
                float v = acc[i][j];
                gsh[(r0+i)*256 + c0i + j] = (gate==2) ? tanhf(v) : sigm(v);
            }
        __syncthreads();
        #pragma unroll
        for (int ii = 0; ii < 4; ii++) {
            int it = tx + 256*ii, r = it>>6, j = it&63;
            float gi = gsh[r*256+j], gf = gsh[r*256+64+j];
            float gg = gsh[r*256+128+j], go = gsh[r*256+192+j];
            float c = gf*creg[ii] + gi*gg;
            float h = go*tanhf(c);
            creg[ii] = c; hsh[it] = h;
            H[(size_t)(t*BB + b0)*64 + it] = h;
        }
        __syncthreads();
    }
}

// ---------- K3: combiner input gates: Gc = [hf|hb] @ Wih_cT + biases ----------
__global__ __launch_bounds__(256) void k3(
    const float* __restrict__ Wc, const float* __restrict__ bic, const float* __restrict__ bhc)
{
    extern __shared__ float sm[];
    float* Wsh = sm;            // [128][140]
    float* Ash = sm + 128*140;  // [32][128]
    const int tx = threadIdx.x, q = blockIdx.y, r0blk = blockIdx.x*32;
    for (int idx = tx; idx < 128*128; idx += 256)
        Wsh[(idx&127)*140 + (idx>>7)] = Wc[(size_t)(q*128 + (idx>>7))*128 + (idx&127)];
    for (int idx = tx; idx < 32*128; idx += 256) {
        int r = idx>>7, k = idx&127, rr = r0blk + r;
        Ash[idx] = (k < 64) ? g_hf[(size_t)rr*64 + k] : g_hb[(size_t)rr*64 + k-64];
    }
    __syncthreads();
    const int c0 = (tx&31)*4, r0 = (tx>>5)*4;
    float acc[4][4];
    #pragma unroll
    for (int j = 0; j < 4; j++) { float bv = bic[q*128+c0+j]+bhc[q*128+c0+j];
        #pragma unroll
        for (int i = 0; i < 4; i++) acc[i][j] = bv; }
    #pragma unroll 2
    for (int k0 = 0; k0 < 128; k0 += 4) {
        float4 a[4];
        #pragma unroll
        for (int i = 0; i < 4; i++) a[i] = *(const float4*)&Ash[(r0+i)*128 + k0];
        #pragma unroll
        for (int kk = 0; kk < 4; kk++) {
            float4 w = *(const float4*)&Wsh[(k0+kk)*140 + c0];
            #pragma unroll
            for (int i = 0; i < 4; i++) {
                float av = kk==0?a[i].x:kk==1?a[i].y:kk==2?a[i].z:a[i].w;
                acc[i][0]+=av*w.x; acc[i][1]+=av*w.y; acc[i][2]+=av*w.z; acc[i][3]+=av*w.w;
            }
        }
    }
    #pragma unroll
    for (int i = 0; i < 4; i++)
        *(float4*)&g_Gc[(size_t)(r0blk+r0+i)*512 + q*128 + c0] =
            make_float4(acc[i][0],acc[i][1],acc[i][2],acc[i][3]);
}

// ---------- K4: combiner recurrence ----------
__global__ __launch_bounds__(256) void k4(
    const float* __restrict__ Whc, const float* __restrict__ h0c, const float* __restrict__ c0c)
{
    extern __shared__ float sm[];
    float* Wsh = sm;             // [128][140]
    float* gsh = sm + 128*140;   // [16][512]
    float* hsh = gsh + 16*512;   // [16][128]
    const int tx = threadIdx.x, b0 = blockIdx.x*16;
    for (int idx = tx; idx < 16*128; idx += 256)
        hsh[idx] = h0c[(b0 + (idx>>7))*128 + (idx&127)];
    float creg[8];
    #pragma unroll
    for (int ii = 0; ii < 8; ii++) {
        int it = tx + 256*ii;
        creg[ii] = c0c[(b0 + (it>>7))*128 + (it&127)];
    }
    const int c0 = (tx&31)*4, r0 = (tx>>5)*2;
    for (int t = 0; t < SS; t++) {
        #pragma unroll 1
        for (int p = 0; p < 4; p++) {
            __syncthreads();
            for (int idx = tx; idx < 128*128; idx += 256)
                Wsh[(idx&127)*140 + (idx>>7)] = Whc[(size_t)(p*128 + (idx>>7))*128 + (idx&127)];
            __syncthreads();
            float acc[2][4];
            #pragma unroll
            for (int i = 0; i < 2; i++) {
                float4 g4 = *(const float4*)&g_Gc[(size_t)(t*BB + b0 + r0 + i)*512 + p*128 + c0];
                acc[i][0]=g4.x; acc[i][1]=g4.y; acc[i][2]=g4.z; acc[i][3]=g4.w;
            }
            #pragma unroll 2
            for (int k0 = 0; k0 < 128; k0 += 4) {
                float4 a[2];
                #pragma unroll
                for (int i = 0; i < 2; i++) a[i] = *(const float4*)&hsh[(r0+i)*128 + k0];
                #pragma unroll
                for (int kk = 0; kk < 4; kk++) {
                    float4 w = *(const float4*)&Wsh[(k0+kk)*140 + c0];
                    #pragma unroll
                    for (int i = 0; i < 2; i++) {
                        float av = kk==0?a[i].x:kk==1?a[i].y:kk==2?a[i].z:a[i].w;
                        acc[i][0]+=av*w.x; acc[i][1]+=av*w.y; acc[i][2]+=av*w.z; acc[i][3]+=av*w.w;
                    }
                }
            }
            #pragma unroll
            for (int i = 0; i < 2; i++)
                #pragma unroll
                for (int j = 0; j < 4; j++) {
                    float v = acc[i][j];
                    gsh[(r0+i)*512 + p*128 + c0 + j] = (p==2) ? tanhf(v) : sigm(v);
                }
        }
        __syncthreads();
        #pragma unroll
        for (int ii = 0; ii < 8; ii++) {
            int it = tx + 256*ii, r = it>>7, j = it&127;
            float gi = gsh[r*512+j], gf = gsh[r*512+128+j];
            float gg = gsh[r*512+256+j], go = gsh[r*512+384+j];
            float c = gf*creg[ii] + gi*gg;
            float h = go*tanhf(c);
            creg[ii] = c; hsh[it] = h;
            if (t == SS-1) g_hL[b0*128 + it] = h;
        }
    }
}

// ---------- K5: out = hL @ WdT + bd  (4096 x 32000, K=128) ----------
__global__ __launch_bounds__(256) void k5(
    const float* __restrict__ Wd, const float* __restrict__ bd, float* __restrict__ out)
{
    extern __shared__ float sm[];
    float* Ash = sm;            // [64 b][128 k]
    float* Bsh = sm + 64*128;   // [128 k][68 v]
    const int tx = threadIdx.x;
    const int v0 = blockIdx.x*64, m0b = blockIdx.y*64;
    for (int idx = tx; idx < 64*32; idx += 256)
        ((float4*)Ash)[idx] = *(const float4*)&g_hL[m0b*128 + idx*4];
    for (int idx = tx; idx < 64*32; idx += 256) {
        int v = idx>>5, k4 = idx&31;
        float4 w = *(const float4*)&Wd[(size_t)(v0+v)*128 + k4*4];
        Bsh[(k4*4+0)*68+v]=w.x; Bsh[(k4*4+1)*68+v]=w.y;
        Bsh[(k4*4+2)*68+v]=w.z; Bsh[(k4*4+3)*68+v]=w.w;
    }
    __syncthreads();
    const int n0 = (tx&15)*4, m0 = (tx>>4)*4;
    float acc[4][4];
    #pragma unroll
    for (int i = 0; i < 4; i++)
        #pragma unroll
        for (int j = 0; j < 4; j++) acc[i][j] = 0.f;
    #pragma unroll 2
    for (int k0 = 0; k0 < 128; k0 += 4) {
        float4 a[4];
        #pragma unroll
        for (int i = 0; i < 4; i++) a[i] = *(const float4*)&Ash[(m0+i)*128 + k0];
        #pragma unroll
        for (int kk = 0; kk < 4; kk++) {
            float4 w = *(const float4*)&Bsh[(k0+kk)*68 + n0];
            #pragma unroll
            for (int i = 0; i < 4; i++) {
                float av = kk==0?a[i].x:kk==1?a[i].y:kk==2?a[i].z:a[i].w;
                acc[i][0]+=av*w.x; acc[i][1]+=av*w.y; acc[i][2]+=av*w.z; acc[i][3]+=av*w.w;
            }
        }
    }
    float4 b4 = *(const float4*)&bd[v0+n0];
    #pragma unroll
    for (int i = 0; i < 4; i++)
        *(float4*)&out[(size_t)(m0b+m0+i)*VV + v0 + n0] =
            make_float4(acc[i][0]+b4.x, acc[i][1]+b4.y, acc[i][2]+b4.z, acc[i][3]+b4.w);
}

extern "C" void kernel_launch(void* const* d_in, const int* in_sizes, int n_in,
                              void* d_out, int out_size) {
    const void*  x     = d_in[0];
    const float* h0f   = (const float*)d_in[1];
    const float* c0f   = (const float*)d_in[2];
    const float* h0b   = (const float*)d_in[3];
    const float* c0b   = (const float*)d_in[4];
    const float* h0c   = (const float*)d_in[5];
    const float* c0c   = (const float*)d_in[6];
    const float* emb   = (const float*)d_in[7];
    const float* Wih_f = (const float*)d_in[8];
    const float* Whh_f = (const float*)d_in[9];
    const float* bih_f = (const float*)d_in[10];
    const float* bhh_f = (const float*)d_in[11];
    const float* Wih_b = (const float*)d_in[12];
    const float* Whh_b = (const float*)d_in[13];
    const float* bih_b = (const float*)d_in[14];
    const float* bhh_b = (const float*)d_in[15];
    const float* Wih_c = (const float*)d_in[16];
    const float* Whh_c = (const float*)d_in[17];
    const float* bih_c = (const float*)d_in[18];
    const float* bhh_c = (const float*)d_in[19];
    const float* Wd    = (const float*)d_in[20];
    const float* bd    = (const float*)d_in[21];
    float* out = (float*)d_out;

    const int s1 = (64*268 + 32*64)*4;
    const int s2 = (64*268 + 16*256 + 16*64)*4;
    const int s3 = (128*140 + 32*128)*4;
    const int s4 = (128*140 + 16*512 + 16*128)*4;
    const int s5 = (64*128 + 128*68)*4;
    cudaFuncSetAttribute(k1, cudaFuncAttributeMaxDynamicSharedMemorySize, s1);
    cudaFuncSetAttribute(k2, cudaFuncAttributeMaxDynamicSharedMemorySize, s2);
    cudaFuncSetAttribute(k3, cudaFuncAttributeMaxDynamicSharedMemorySize, s3);
    cudaFuncSetAttribute(k4, cudaFuncAttributeMaxDynamicSharedMemorySize, s4);
    cudaFuncSetAttribute(k5, cudaFuncAttributeMaxDynamicSharedMemorySize, s5);

    k1<<<dim3(SB/32, 2), 256, s1>>>(x, emb, Wih_f, bih_f, bhh_f, Wih_b, bih_b, bhh_b);
    k2<<<dim3(BB/16, 2), 256, s2>>>(Whh_f, h0f, c0f, Whh_b, h0b, c0b);
    k3<<<dim3(SB/32, 4), 256, s3>>>(Wih_c, bih_c, bhh_c);
    k4<<<dim3(BB/16, 1), 256, s4>>>(Whh_c, h0c, c0c);
    k5<<<dim3(VV/64, BB/64), 256, s5>>>(Wd, bd, out);
}

// round 4
// speedup vs baseline: 2.2935x; 2.2935x over previous
#include <cuda_runtime.h>
#include <math.h>

#define SS 32
#define EE 64
#define VV 32000
#define BB 4096
#define SB (SS*BB)

__device__ float g_Gf[(size_t)SB*256];
__device__ float g_Gb[(size_t)SB*256];
__device__ float g_hf[(size_t)SB*EE];
__device__ float g_hb[(size_t)SB*EE];
__device__ float g_Gc[(size_t)SB*512];
__device__ float g_hL[BB*128];

__device__ __forceinline__ float sigm(float x){ return 1.0f/(1.0f+__expf(-x)); }
__device__ __forceinline__ unsigned f2t(float f){
    unsigned u; asm("cvt.rna.tf32.f32 %0, %1;" : "=r"(u) : "f"(f)); return u;
}
__device__ __forceinline__ void mma8(float* c, const unsigned* a, const unsigned* b){
    asm volatile("mma.sync.aligned.m16n8k8.row.col.f32.tf32.tf32.f32 "
        "{%0,%1,%2,%3}, {%4,%5,%6,%7}, {%8,%9}, {%0,%1,%2,%3};"
        : "+f"(c[0]), "+f"(c[1]), "+f"(c[2]), "+f"(c[3])
        : "r"(a[0]), "r"(a[1]), "r"(a[2]), "r"(a[3]), "r"(b[0]), "r"(b[1]));
}
// A m16k8 fragment from row-major [m][k] (pad) tf32 smem
__device__ __forceinline__ void ldA(unsigned* a, const unsigned* S, int m0, int k0,
                                    int pad, int gid, int tig){
    a[0] = S[(m0+gid  )*pad + k0+tig  ];
    a[1] = S[(m0+gid+8)*pad + k0+tig  ];
    a[2] = S[(m0+gid  )*pad + k0+tig+4];
    a[3] = S[(m0+gid+8)*pad + k0+tig+4];
}
// B n8k8 fragment (col-major B == row-major [n][k]) from (pad) tf32 smem
__device__ __forceinline__ void ldB(unsigned* b, const unsigned* S, int n0, int k0,
                                    int pad, int gid, int tig){
    b[0] = S[(n0+gid)*pad + k0+tig  ];
    b[1] = S[(n0+gid)*pad + k0+tig+4];
}

// ---------- K1: G = emb[x] @ Wih^T + bih + bhh (fwd & bwd). M=64/CTA, N=256, K=64
__global__ __launch_bounds__(256) void k1(const void* __restrict__ xraw,
    const float* __restrict__ emb,
    const float* __restrict__ Wf, const float* __restrict__ bif, const float* __restrict__ bhf,
    const float* __restrict__ Wb, const float* __restrict__ bib, const float* __restrict__ bhb)
{
    extern __shared__ unsigned sm[];
    unsigned* Wsh = sm;             // [256][68]
    unsigned* Ash = sm + 256*68;    // [64][68]
    __shared__ int s64;
    const int tx = threadIdx.x, dir = blockIdx.y;
    const float* W  = dir ? Wb  : Wf;
    const float* bi = dir ? bib : bif;
    const float* bh = dir ? bhb : bhf;
    float* G = dir ? g_Gb : g_Gf;
    if (tx == 0) {
        const int* p = (const int*)xraw; int f = 1;
        for (int q = 0; q < 64; q++) if (p[2*q+1] != 0) { f = 0; break; }
        s64 = f;
    }
    for (int idx = tx; idx < 256*16; idx += 256) {
        int n = idx>>4, k4 = idx&15;
        float4 w = *(const float4*)&W[n*64 + k4*4];
        *(uint4*)&Wsh[n*68 + k4*4] = make_uint4(f2t(w.x),f2t(w.y),f2t(w.z),f2t(w.w));
    }
    __syncthreads();
    const int r0blk = blockIdx.x*64;
    {
        const long long* x64 = (const long long*)xraw;
        const int* x32 = (const int*)xraw;
        const int is64 = s64;
        for (int idx = tx; idx < 64*16; idx += 256) {
            int r = idx>>4, k4 = idx&15, rr = r0blk + r, pos;
            if (dir) { int t = rr>>12, b = rr&4095; pos = (SS-1-t)*BB + b; }
            else pos = rr;
            int tok = is64 ? (int)x64[pos] : x32[pos];
            float4 e = *(const float4*)&emb[tok*64 + k4*4];
            *(uint4*)&Ash[r*68 + k4*4] = make_uint4(f2t(e.x),f2t(e.y),f2t(e.z),f2t(e.w));
        }
    }
    __syncthreads();
    const int lid = tx&31, wid = tx>>5, gid = lid>>2, tig = lid&3;
    const int wm = wid>>2, wn = wid&3;          // m: wm*32 (2 blocks), n: wn*64 (8 blocks)
    float acc[2][8][4];
    #pragma unroll
    for (int nb = 0; nb < 8; nb++) {
        int col = wn*64 + nb*8 + tig*2;
        float b0v = bi[col]+bh[col], b1v = bi[col+1]+bh[col+1];
        #pragma unroll
        for (int mb = 0; mb < 2; mb++) {
            acc[mb][nb][0]=b0v; acc[mb][nb][1]=b1v; acc[mb][nb][2]=b0v; acc[mb][nb][3]=b1v;
        }
    }
    #pragma unroll
    for (int k0 = 0; k0 < 64; k0 += 8) {
        unsigned a[2][4], b[8][2];
        #pragma unroll
        for (int mb = 0; mb < 2; mb++) ldA(a[mb], Ash, wm*32+mb*16, k0, 68, gid, tig);
        #pragma unroll
        for (int nb = 0; nb < 8; nb++) ldB(b[nb], Wsh, wn*64+nb*8, k0, 68, gid, tig);
        #pragma unroll
        for (int mb = 0; mb < 2; mb++)
            #pragma unroll
            for (int nb = 0; nb < 8; nb++) mma8(acc[mb][nb], a[mb], b[nb]);
    }
    #pragma unroll
    for (int mb = 0; mb < 2; mb++)
        #pragma unroll
        for (int nb = 0; nb < 8; nb++) {
            int row = r0blk + wm*32 + mb*16 + gid;
            int col = wn*64 + nb*8 + tig*2;
            *(float2*)&G[(size_t)row*256 + col]     = make_float2(acc[mb][nb][0],acc[mb][nb][1]);
            *(float2*)&G[(size_t)(row+8)*256 + col] = make_float2(acc[mb][nb][2],acc[mb][nb][3]);
        }
}

// ---------- K2: fwd/bwd recurrence (persistent, 16 batch rows/CTA), mma per step
__global__ __launch_bounds__(256) void k2(
    const float* __restrict__ Whf, const float* __restrict__ h0f, const float* __restrict__ c0f,
    const float* __restrict__ Whb, const float* __restrict__ h0b, const float* __restrict__ c0b)
{
    extern __shared__ unsigned sm[];
    unsigned* Wsh = sm;             // [256][68]
    unsigned* hsh = sm + 256*68;    // [16][68]
    float* gsh = (float*)(sm + 256*68 + 16*68);   // [16][260]
    const int tx = threadIdx.x, dir = blockIdx.y;
    const float* Whh = dir ? Whb : Whf;
    const float* h0  = dir ? h0b : h0f;
    const float* c0  = dir ? c0b : c0f;
    const float* G   = dir ? g_Gb : g_Gf;
    float* H = dir ? g_hb : g_hf;
    const int b0 = blockIdx.x*16;
    for (int idx = tx; idx < 256*16; idx += 256) {
        int n = idx>>4, k4 = idx&15;
        float4 w = *(const float4*)&Whh[n*64 + k4*4];
        *(uint4*)&Wsh[n*68 + k4*4] = make_uint4(f2t(w.x),f2t(w.y),f2t(w.z),f2t(w.w));
    }
    for (int idx = tx; idx < 16*64; idx += 256)
        hsh[(idx>>6)*68 + (idx&63)] = f2t(h0[(b0+(idx>>6))*64 + (idx&63)]);
    float creg[4];
    #pragma unroll
    for (int ii = 0; ii < 4; ii++) {
        int it = tx + 256*ii;
        creg[ii] = c0[(b0+(it>>6))*64 + (it&63)];
    }
    __syncthreads();
    const int lid = tx&31, wid = tx>>5, gid = lid>>2, tig = lid&3;
    for (int t = 0; t < SS; t++) {
        float acc[4][4];
        #pragma unroll
        for (int nb = 0; nb < 4; nb++) {
            int col = wid*32 + nb*8 + tig*2;
            float2 g0 = *(const float2*)&G[(size_t)(t*BB+b0+gid)*256 + col];
            float2 g1 = *(const float2*)&G[(size_t)(t*BB+b0+gid+8)*256 + col];
            acc[nb][0]=g0.x; acc[nb][1]=g0.y; acc[nb][2]=g1.x; acc[nb][3]=g1.y;
        }
        #pragma unroll
        for (int k0 = 0; k0 < 64; k0 += 8) {
            unsigned a[4], b[4][2];
            ldA(a, hsh, 0, k0, 68, gid, tig);
            #pragma unroll
            for (int nb = 0; nb < 4; nb++) ldB(b[nb], Wsh, wid*32+nb*8, k0, 68, gid, tig);
            #pragma unroll
            for (int nb = 0; nb < 4; nb++) mma8(acc[nb], a, b[nb]);
        }
        #pragma unroll
        for (int nb = 0; nb < 4; nb++) {
            int col = wid*32 + nb*8 + tig*2;
            int gate = col>>6;
            float v0=acc[nb][0], v1=acc[nb][1], v2=acc[nb][2], v3=acc[nb][3];
            if (gate == 2) { v0=tanhf(v0); v1=tanhf(v1); v2=tanhf(v2); v3=tanhf(v3); }
            else           { v0=sigm(v0);  v1=sigm(v1);  v2=sigm(v2);  v3=sigm(v3); }
            *(float2*)&gsh[gid*260 + col]     = make_float2(v0,v1);
            *(float2*)&gsh[(gid+8)*260 + col] = make_float2(v2,v3);
        }
        __syncthreads();
        #pragma unroll
        for (int ii = 0; ii < 4; ii++) {
            int it = tx + 256*ii, r = it>>6, j = it&63;
            float gi = gsh[r*260+j],     gf = gsh[r*260+64+j];
            float gg = gsh[r*260+128+j], go = gsh[r*260+192+j];
            float c = gf*creg[ii] + gi*gg;
            float h = go*tanhf(c);
            creg[ii] = c;
            hsh[r*68+j] = f2t(h);
            H[(size_t)(t*BB+b0)*64 + it] = h;
        }
        __syncthreads();
    }
}

// ---------- K3: Gc = [hf|hb] @ Wih_c^T + biases. M=128/CTA, N=128/CTA(q), K=128
__global__ __launch_bounds__(256) void k3(
    const float* __restrict__ Wc, const float* __restrict__ bic, const float* __restrict__ bhc)
{
    extern __shared__ unsigned sm[];
    unsigned* Bsh = sm;             // [128][132]
    unsigned* Ash = sm + 128*132;   // [128][132]
    const int tx = threadIdx.x, q = blockIdx.y, r0blk = blockIdx.x*128;
    for (int idx = tx; idx < 128*32; idx += 256) {
        int n = idx>>5, k4 = idx&31;
        float4 w = *(const float4*)&Wc[(size_t)(q*128+n)*128 + k4*4];
        *(uint4*)&Bsh[n*132 + k4*4] = make_uint4(f2t(w.x),f2t(w.y),f2t(w.z),f2t(w.w));
    }
    for (int idx = tx; idx < 128*32; idx += 256) {
        int r = idx>>5, k4 = idx&31;
        const float* src = (k4 < 16) ? &g_hf[(size_t)(r0blk+r)*64 + k4*4]
                                     : &g_hb[(size_t)(r0blk+r)*64 + (k4-16)*4];
        float4 e = *(const float4*)src;
        *(uint4*)&Ash[r*132 + k4*4] = make_uint4(f2t(e.x),f2t(e.y),f2t(e.z),f2t(e.w));
    }
    __syncthreads();
    const int lid = tx&31, wid = tx>>5, gid = lid>>2, tig = lid&3;
    const int wm = wid>>2, wn = wid&3;         // m: wm*64 (4 blocks), n: wn*32 (4 blocks)
    float acc[4][4][4];
    #pragma unroll
    for (int nb = 0; nb < 4; nb++) {
        int col = q*128 + wn*32 + nb*8 + tig*2;
        float b0v = bic[col]+bhc[col], b1v = bic[col+1]+bhc[col+1];
        #pragma unroll
        for (int mb = 0; mb < 4; mb++) {
            acc[mb][nb][0]=b0v; acc[mb][nb][1]=b1v; acc[mb][nb][2]=b0v; acc[mb][nb][3]=b1v;
        }
    }
    #pragma unroll
    for (int k0 = 0; k0 < 128; k0 += 8) {
        unsigned a[4][4], b[4][2];
        #pragma unroll
        for (int mb = 0; mb < 4; mb++) ldA(a[mb], Ash, wm*64+mb*16, k0, 132, gid, tig);
        #pragma unroll
        for (int nb = 0; nb < 4; nb++) ldB(b[nb], Bsh, wn*32+nb*8, k0, 132, gid, tig);
        #pragma unroll
        for (int mb = 0; mb < 4; mb++)
            #pragma unroll
            for (int nb = 0; nb < 4; nb++) mma8(acc[mb][nb], a[mb], b[nb]);
    }
    #pragma unroll
    for (int mb = 0; mb < 4; mb++)
        #pragma unroll
        for (int nb = 0; nb < 4; nb++) {
            int row = r0blk + wm*64 + mb*16 + gid;
            int col = q*128 + wn*32 + nb*8 + tig*2;
            *(float2*)&g_Gc[(size_t)row*512 + col]     = make_float2(acc[mb][nb][0],acc[mb][nb][1]);
            *(float2*)&g_Gc[(size_t)(row+8)*512 + col] = make_float2(acc[mb][nb][2],acc[mb][nb][3]);
        }
}

// ---------- K4: combiner recurrence (persistent, 32 batch rows/CTA, weight streaming)
__global__ __launch_bounds__(256) void k4(
    const float* __restrict__ Whc, const float* __restrict__ h0c, const float* __restrict__ c0c)
{
    extern __shared__ unsigned sm[];
    unsigned* Wsh = sm;              // [128][132]
    unsigned* hsh = sm + 128*132;    // [32][132]
    float* gsh = (float*)(sm + 128*132 + 32*132);   // [32][516]
    const int tx = threadIdx.x, b0 = blockIdx.x*32;
    for (int idx = tx; idx < 32*128; idx += 256)
        hsh[(idx>>7)*132 + (idx&127)] = f2t(h0c[(b0+(idx>>7))*128 + (idx&127)]);
    float creg[16];
    #pragma unroll
    for (int ii = 0; ii < 16; ii++) {
        int it = tx + 256*ii;
        creg[ii] = c0c[(b0+(it>>7))*128 + (it&127)];
    }
    const int lid = tx&31, wid = tx>>5, gid = lid>>2, tig = lid&3;
    for (int t = 0; t < SS; t++) {
        #pragma unroll 1
        for (int p = 0; p < 4; p++) {
            __syncthreads();
            for (int idx = tx; idx < 128*32; idx += 256) {
                int n = idx>>5, k4 = idx&31;
                float4 w = *(const float4*)&Whc[(size_t)(p*128+n)*128 + k4*4];
                *(uint4*)&Wsh[n*132 + k4*4] = make_uint4(f2t(w.x),f2t(w.y),f2t(w.z),f2t(w.w));
            }
            __syncthreads();
            float acc[2][2][4];
            #pragma unroll
            for (int mb = 0; mb < 2; mb++)
                #pragma unroll
                for (int nb = 0; nb < 2; nb++) {
                    int row = b0 + mb*16 + gid;
                    int col = p*128 + wid*16 + nb*8 + tig*2;
                    float2 g0 = *(const float2*)&g_Gc[(size_t)(t*BB+row)*512 + col];
                    float2 g1 = *(const float2*)&g_Gc[(size_t)(t*BB+row+8)*512 + col];
                    acc[mb][nb][0]=g0.x; acc[mb][nb][1]=g0.y; acc[mb][nb][2]=g1.x; acc[mb][nb][3]=g1.y;
                }
            #pragma unroll
            for (int k0 = 0; k0 < 128; k0 += 8) {
                unsigned a[2][4], b[2][2];
                #pragma unroll
                for (int mb = 0; mb < 2; mb++) ldA(a[mb], hsh, mb*16, k0, 132, gid, tig);
                #pragma unroll
                for (int nb = 0; nb < 2; nb++) ldB(b[nb], Wsh, wid*16+nb*8, k0, 132, gid, tig);
                #pragma unroll
                for (int mb = 0; mb < 2; mb++)
                    #pragma unroll
                    for (int nb = 0; nb < 2; nb++) mma8(acc[mb][nb], a[mb], b[nb]);
            }
            #pragma unroll
            for (int mb = 0; mb < 2; mb++)
                #pragma unroll
                for (int nb = 0; nb < 2; nb++) {
                    int srow = mb*16 + gid;
                    int scol = p*128 + wid*16 + nb*8 + tig*2;
                    float v0=acc[mb][nb][0], v1=acc[mb][nb][1];
                    float v2=acc[mb][nb][2], v3=acc[mb][nb][3];
                    if (p == 2) { v0=tanhf(v0); v1=tanhf(v1); v2=tanhf(v2); v3=tanhf(v3); }
                    else        { v0=sigm(v0);  v1=sigm(v1);  v2=sigm(v2);  v3=sigm(v3); }
                    *(float2*)&gsh[srow*516 + scol]     = make_float2(v0,v1);
                    *(float2*)&gsh[(srow+8)*516 + scol] = make_float2(v2,v3);
                }
        }
        __syncthreads();
        #pragma unroll
        for (int ii = 0; ii < 16; ii++) {
            int it = tx + 256*ii, r = it>>7, j = it&127;
            float gi = gsh[r*516+j],     gf = gsh[r*516+128+j];
            float gg = gsh[r*516+256+j], go = gsh[r*516+384+j];
            float c = gf*creg[ii] + gi*gg;
            float h = go*tanhf(c);
            creg[ii] = c;
            hsh[r*132+j] = f2t(h);
            if (t == SS-1) g_hL[(b0+r)*128 + j] = h;
        }
    }
}

// ---------- K5: out = hL @ Wd^T + bd. 64x128 CTA tile, K=128
__global__ __launch_bounds__(256) void k5(
    const float* __restrict__ Wd, const float* __restrict__ bd, float* __restrict__ out)
{
    extern __shared__ unsigned sm[];
    unsigned* Bsh = sm;             // [128][132]
    unsigned* Ash = sm + 128*132;   // [64][132]
    const int tx = threadIdx.x;
    const int v0 = blockIdx.x*128, m0b = blockIdx.y*64;
    for (int idx = tx; idx < 128*32; idx += 256) {
        int n = idx>>5, k4 = idx&31;
        float4 w = *(const float4*)&Wd[(size_t)(v0+n)*128 + k4*4];
        *(uint4*)&Bsh[n*132 + k4*4] = make_uint4(f2t(w.x),f2t(w.y),f2t(w.z),f2t(w.w));
    }
    for (int idx = tx; idx < 64*32; idx += 256) {
        int m = idx>>5, k4 = idx&31;
        float4 e = *(const float4*)&g_hL[(m0b+m)*128 + k4*4];
        *(uint4*)&Ash[m*132 + k4*4] = make_uint4(f2t(e.x),f2t(e.y),f2t(e.z),f2t(e.w));
    }
    __syncthreads();
    const int lid = tx&31, wid = tx>>5, gid = lid>>2, tig = lid&3;
    const int wm = wid>>2, wn = wid&3;         // m: wm*32 (2 blocks), n: wn*32 (4 blocks)
    float acc[2][4][4];
    #pragma unroll
    for (int mb = 0; mb < 2; mb++)
        #pragma unroll
        for (int nb = 0; nb < 4; nb++)
            #pragma unroll
            for (int r = 0; r < 4; r++) acc[mb][nb][r] = 0.f;
    #pragma unroll
    for (int k0 = 0; k0 < 128; k0 += 8) {
        unsigned a[2][4], b[4][2];
        #pragma unroll
        for (int mb = 0; mb < 2; mb++) ldA(a[mb], Ash, wm*32+mb*16, k0, 132, gid, tig);
        #pragma unroll
        for (int nb = 0; nb < 4; nb++) ldB(b[nb], Bsh, wn*32+nb*8, k0, 132, gid, tig);
        #pragma unroll
        for (int mb = 0; mb < 2; mb++)
            #pragma unroll
            for (int nb = 0; nb < 4; nb++) mma8(acc[mb][nb], a[mb], b[nb]);
    }
    #pragma unroll
    for (int mb = 0; mb < 2; mb++)
        #pragma unroll
        for (int nb = 0; nb < 4; nb++) {
            int row = m0b + wm*32 + mb*16 + gid;
            int col = v0 + wn*32 + nb*8 + tig*2;
            float2 bb = *(const float2*)&bd[col];
            *(float2*)&out[(size_t)row*VV + col] =
                make_float2(acc[mb][nb][0]+bb.x, acc[mb][nb][1]+bb.y);
            *(float2*)&out[(size_t)(row+8)*VV + col] =
                make_float2(acc[mb][nb][2]+bb.x, acc[mb][nb][3]+bb.y);
        }
}

extern "C" void kernel_launch(void* const* d_in, const int* in_sizes, int n_in,
                              void* d_out, int out_size) {
    const void*  x     = d_in[0];
    const float* h0f   = (const float*)d_in[1];
    const float* c0f   = (const float*)d_in[2];
    const float* h0b   = (const float*)d_in[3];
    const float* c0b   = (const float*)d_in[4];
    const float* h0c   = (const float*)d_in[5];
    const float* c0c   = (const float*)d_in[6];
    const float* emb   = (const float*)d_in[7];
    const float* Wih_f = (const float*)d_in[8];
    const float* Whh_f = (const float*)d_in[9];
    const float* bih_f = (const float*)d_in[10];
    const float* bhh_f = (const float*)d_in[11];
    const float* Wih_b = (const float*)d_in[12];
    const float* Whh_b = (const float*)d_in[13];
    const float* bih_b = (const float*)d_in[14];
    const float* bhh_b = (const float*)d_in[15];
    const float* Wih_c = (const float*)d_in[16];
    const float* Whh_c = (const float*)d_in[17];
    const float* bih_c = (const float*)d_in[18];
    const float* bhh_c = (const float*)d_in[19];
    const float* Wd    = (const float*)d_in[20];
    const float* bd    = (const float*)d_in[21];
    float* out = (float*)d_out;

    const int s1 = (256*68 + 64*68)*4;              // 87040
    const int s2 = (256*68 + 16*68 + 16*260)*4;     // 90624
    const int s3 = (128*132 + 128*132)*4;           // 135168
    const int s4 = (128*132 + 32*132 + 32*516)*4;   // 150528
    const int s5 = (128*132 + 64*132)*4;            // 101376
    cudaFuncSetAttribute(k1, cudaFuncAttributeMaxDynamicSharedMemorySize, s1);
    cudaFuncSetAttribute(k2, cudaFuncAttributeMaxDynamicSharedMemorySize, s2);
    cudaFuncSetAttribute(k3, cudaFuncAttributeMaxDynamicSharedMemorySize, s3);
    cudaFuncSetAttribute(k4, cudaFuncAttributeMaxDynamicSharedMemorySize, s4);
    cudaFuncSetAttribute(k5, cudaFuncAttributeMaxDynamicSharedMemorySize, s5);

    k1<<<dim3(SB/64, 2), 256, s1>>>(x, emb, Wih_f, bih_f, bhh_f, Wih_b, bih_b, bhh_b);
    k2<<<dim3(BB/16, 2), 256, s2>>>(Whh_f, h0f, c0f, Whh_b, h0b, c0b);
    k3<<<dim3(SB/128, 4), 256, s3>>>(Wih_c, bih_c, bhh_c);
    k4<<<dim3(BB/32, 1), 256, s4>>>(Whh_c, h0c, c0c);
    k5<<<dim3(VV/128, BB/64), 256, s5>>>(Wd, bd, out);
}

// round 5
// speedup vs baseline: 3.8288x; 1.6694x over previous
#include <cuda_runtime.h>
#include <math.h>

#define SS 32
#define EE 64
#define VV 32000
#define BB 4096
#define SB (SS*BB)

__device__ float g_hf[(size_t)SB*EE];
__device__ float g_hb[(size_t)SB*EE];
__device__ float g_Gc[(size_t)SB*512];
__device__ float g_hL[BB*128];

__device__ __forceinline__ float sigm(float x){ return 1.0f/(1.0f+__expf(-x)); }
__device__ __forceinline__ unsigned sptr(const void* p){
    return (unsigned)__cvta_generic_to_shared(p);
}
__device__ __forceinline__ void cpa16(unsigned d, const void* s){
    asm volatile("cp.async.cg.shared.global [%0], [%1], 16;" :: "r"(d), "l"(s));
}
#define CPCOMMIT() asm volatile("cp.async.commit_group;")
#define CPWAIT(n)  asm volatile("cp.async.wait_group %0;" :: "n"(n))

__device__ __forceinline__ void mma8(float* c, const unsigned* a, const unsigned* b){
    asm volatile("mma.sync.aligned.m16n8k8.row.col.f32.tf32.tf32.f32 "
        "{%0,%1,%2,%3}, {%4,%5,%6,%7}, {%8,%9}, {%0,%1,%2,%3};"
        : "+f"(c[0]), "+f"(c[1]), "+f"(c[2]), "+f"(c[3])
        : "r"(a[0]), "r"(a[1]), "r"(a[2]), "r"(a[3]), "r"(b[0]), "r"(b[1]));
}
__device__ __forceinline__ void ldA(unsigned* a, const unsigned* S, int m0, int k0,
                                    int pad, int gid, int tig){
    a[0] = S[(m0+gid  )*pad + k0+tig  ];
    a[1] = S[(m0+gid+8)*pad + k0+tig  ];
    a[2] = S[(m0+gid  )*pad + k0+tig+4];
    a[3] = S[(m0+gid+8)*pad + k0+tig+4];
}
__device__ __forceinline__ void ldB(unsigned* b, const unsigned* S, int n0, int k0,
                                    int pad, int gid, int tig){
    b[0] = S[(n0+gid)*pad + k0+tig  ];
    b[1] = S[(n0+gid)*pad + k0+tig+4];
}

// ======== K2F: fused embed + input-gate GEMM + fwd/bwd LSTM recurrence ========
// grid (BB/32, 2), 256 thr. Weights Wih+Whh resident in smem; emb prefetched.
__global__ __launch_bounds__(256) void k2f(const void* __restrict__ xraw,
    const float* __restrict__ emb,
    const float* __restrict__ Wif, const float* __restrict__ Whf_,
    const float* __restrict__ bif, const float* __restrict__ bhf,
    const float* __restrict__ h0f, const float* __restrict__ c0f,
    const float* __restrict__ Wib, const float* __restrict__ Whb_,
    const float* __restrict__ bib, const float* __restrict__ bhb,
    const float* __restrict__ h0b, const float* __restrict__ c0b)
{
    extern __shared__ unsigned sm[];
    unsigned* Wi = sm;              // [256][68]
    unsigned* Wh = sm + 17408;      // [256][68]
    unsigned* As = sm + 34816;      // 2 x [32][68]
    unsigned* Hs = sm + 39168;      // [32][68]
    int*      Tk = (int*)(sm + 41344); // [32 t][32 r]
    __shared__ int s64;
    const int tx = threadIdx.x, dir = blockIdx.y, b0 = blockIdx.x*32;
    const float* Wih = dir ? Wib : Wif;
    const float* Whh = dir ? Whb_ : Whf_;
    const float* bi  = dir ? bib : bif;
    const float* bh  = dir ? bhb : bhf;
    const float* h0  = dir ? h0b : h0f;
    const float* c0  = dir ? c0b : c0f;
    float* H = dir ? g_hb : g_hf;

    for (int idx = tx; idx < 256*16; idx += 256) {
        int n = idx>>4, c = idx&15;
        cpa16(sptr(&Wi[n*68 + c*4]), &Wih[n*64 + c*4]);
        cpa16(sptr(&Wh[n*68 + c*4]), &Whh[n*64 + c*4]);
    }
    CPCOMMIT();
    if (tx == 0) {
        const int* p = (const int*)xraw; int f = 1;
        for (int q = 0; q < 64; q++) if (p[2*q+1] != 0) { f = 0; break; }
        s64 = f;
    }
    __syncthreads();
    {
        const long long* x64 = (const long long*)xraw;
        const int* x32 = (const int*)xraw;
        const int is64 = s64;
        for (int idx = tx; idx < 1024; idx += 256) {
            int t = idx>>5, r = idx&31;
            int pos = dir ? (SS-1-t)*BB + b0 + r : t*BB + b0 + r;
            Tk[idx] = is64 ? (int)x64[pos] : x32[pos];
        }
    }
    for (int idx = tx; idx < 32*64; idx += 256)
        Hs[(idx>>6)*68 + (idx&63)] = __float_as_uint(h0[(b0+(idx>>6))*64 + (idx&63)]);
    __syncthreads();
    for (int idx = tx; idx < 32*16; idx += 256) {    // prefetch emb for t=0
        int r = idx>>4, c = idx&15;
        cpa16(sptr(&As[r*68 + c*4]), &emb[Tk[r]*64 + c*4]);
    }
    CPCOMMIT();

    const int lid = tx&31, wid = tx>>5, gid = lid>>2, tig = lid&3;
    const int jc = wid*8 + tig*2;
    float bA[4][2];
    #pragma unroll
    for (int g = 0; g < 4; g++) {
        bA[g][0] = bi[g*64+jc]   + bh[g*64+jc];
        bA[g][1] = bi[g*64+jc+1] + bh[g*64+jc+1];
    }
    float creg[2][4];
    #pragma unroll
    for (int mb = 0; mb < 2; mb++) {
        float2 c1 = *(const float2*)&c0[(b0+mb*16+gid)*64 + jc];
        float2 c2 = *(const float2*)&c0[(b0+mb*16+gid+8)*64 + jc];
        creg[mb][0]=c1.x; creg[mb][1]=c1.y; creg[mb][2]=c2.x; creg[mb][3]=c2.y;
    }
    for (int t = 0; t < SS; t++) {
        if (t < SS-1) {
            for (int idx = tx; idx < 32*16; idx += 256) {
                int r = idx>>4, c = idx&15;
                cpa16(sptr(&As[((t+1)&1)*2176 + r*68 + c*4]), &emb[Tk[(t+1)*32+r]*64 + c*4]);
            }
            CPCOMMIT(); CPWAIT(1);
        } else CPWAIT(0);
        __syncthreads();
        const unsigned* Ab = As + (t&1)*2176;
        float acc[2][4][4];
        #pragma unroll
        for (int mb = 0; mb < 2; mb++)
            #pragma unroll
            for (int g = 0; g < 4; g++) {
                acc[mb][g][0]=bA[g][0]; acc[mb][g][1]=bA[g][1];
                acc[mb][g][2]=bA[g][0]; acc[mb][g][3]=bA[g][1];
            }
        #pragma unroll
        for (int k0 = 0; k0 < 64; k0 += 8) {
            unsigned a[2][4], bf[4][2];
            #pragma unroll
            for (int mb = 0; mb < 2; mb++) ldA(a[mb], Ab, mb*16, k0, 68, gid, tig);
            #pragma unroll
            for (int g = 0; g < 4; g++) ldB(bf[g], Wi, g*64 + wid*8, k0, 68, gid, tig);
            #pragma unroll
            for (int mb = 0; mb < 2; mb++)
                #pragma unroll
                for (int g = 0; g < 4; g++) mma8(acc[mb][g], a[mb], bf[g]);
        }
        #pragma unroll
        for (int k0 = 0; k0 < 64; k0 += 8) {
            unsigned a[2][4], bf[4][2];
            #pragma unroll
            for (int mb = 0; mb < 2; mb++) ldA(a[mb], Hs, mb*16, k0, 68, gid, tig);
            #pragma unroll
            for (int g = 0; g < 4; g++) ldB(bf[g], Wh, g*64 + wid*8, k0, 68, gid, tig);
            #pragma unroll
            for (int mb = 0; mb < 2; mb++)
                #pragma unroll
                for (int g = 0; g < 4; g++) mma8(acc[mb][g], a[mb], bf[g]);
        }
        __syncthreads();   // all Hs reads done before rewrite
        #pragma unroll
        for (int mb = 0; mb < 2; mb++) {
            float hv[4];
            #pragma unroll
            for (int q = 0; q < 4; q++) {
                float iv = sigm(acc[mb][0][q]);
                float fv = sigm(acc[mb][1][q]);
                float gv = tanhf(acc[mb][2][q]);
                float ov = sigm(acc[mb][3][q]);
                float c = fv*creg[mb][q] + iv*gv;
                hv[q] = ov*tanhf(c);
                creg[mb][q] = c;
            }
            int r1 = mb*16 + gid, r2 = r1 + 8;
            Hs[r1*68 + jc]   = __float_as_uint(hv[0]);
            Hs[r1*68 + jc+1] = __float_as_uint(hv[1]);
            Hs[r2*68 + jc]   = __float_as_uint(hv[2]);
            Hs[r2*68 + jc+1] = __float_as_uint(hv[3]);
            *(float2*)&H[(size_t)(t*BB + b0 + r1)*64 + jc] = make_float2(hv[0],hv[1]);
            *(float2*)&H[(size_t)(t*BB + b0 + r2)*64 + jc] = make_float2(hv[2],hv[3]);
        }
    }
}

// ======== K3: Gc = [hf|hb] @ Wih_c^T + biases ========
__global__ __launch_bounds__(256) void k3(
    const float* __restrict__ Wc, const float* __restrict__ bic, const float* __restrict__ bhc)
{
    extern __shared__ unsigned sm[];
    unsigned* Bs = sm;              // [128][132]
    unsigned* As = sm + 128*132;    // [128][132]
    const int tx = threadIdx.x, q = blockIdx.y, r0blk = blockIdx.x*128;
    for (int idx = tx; idx < 128*32; idx += 256) {
        int n = idx>>5, c = idx&31;
        cpa16(sptr(&Bs[n*132 + c*4]), &Wc[(size_t)(q*128+n)*128 + c*4]);
    }
    for (int idx = tx; idx < 128*32; idx += 256) {
        int r = idx>>5, c = idx&31;
        const float* src = (c < 16) ? &g_hf[(size_t)(r0blk+r)*64 + c*4]
                                    : &g_hb[(size_t)(r0blk+r)*64 + (c-16)*4];
        cpa16(sptr(&As[r*132 + c*4]), src);
    }
    CPCOMMIT(); CPWAIT(0);
    __syncthreads();
    const int lid = tx&31, wid = tx>>5, gid = lid>>2, tig = lid&3;
    const int wm = wid>>2, wn = wid&3;
    float acc[4][4][4];
    #pragma unroll
    for (int nb = 0; nb < 4; nb++) {
        int col = q*128 + wn*32 + nb*8 + tig*2;
        float b0v = bic[col]+bhc[col], b1v = bic[col+1]+bhc[col+1];
        #pragma unroll
        for (int mb = 0; mb < 4; mb++) {
            acc[mb][nb][0]=b0v; acc[mb][nb][1]=b1v; acc[mb][nb][2]=b0v; acc[mb][nb][3]=b1v;
        }
    }
    #pragma unroll
    for (int k0 = 0; k0 < 128; k0 += 8) {
        unsigned a[4][4], b[4][2];
        #pragma unroll
        for (int mb = 0; mb < 4; mb++) ldA(a[mb], As, wm*64+mb*16, k0, 132, gid, tig);
        #pragma unroll
        for (int nb = 0; nb < 4; nb++) ldB(b[nb], Bs, wn*32+nb*8, k0, 132, gid, tig);
        #pragma unroll
        for (int mb = 0; mb < 4; mb++)
            #pragma unroll
            for (int nb = 0; nb < 4; nb++) mma8(acc[mb][nb], a[mb], b[nb]);
    }
    #pragma unroll
    for (int mb = 0; mb < 4; mb++)
        #pragma unroll
        for (int nb = 0; nb < 4; nb++) {
            int row = r0blk + wm*64 + mb*16 + gid;
            int col = q*128 + wn*32 + nb*8 + tig*2;
            *(float2*)&g_Gc[(size_t)row*512 + col]     = make_float2(acc[mb][nb][0],acc[mb][nb][1]);
            *(float2*)&g_Gc[(size_t)(row+8)*512 + col] = make_float2(acc[mb][nb][2],acc[mb][nb][3]);
        }
}

// ======== K4: combiner recurrence, double-buffered weight streaming ========
__global__ __launch_bounds__(256) void k4(
    const float* __restrict__ Whc, const float* __restrict__ h0c, const float* __restrict__ c0c)
{
    extern __shared__ unsigned sm[];
    unsigned* Ws = sm;              // 2 x [128][132]
    unsigned* Hs = sm + 2*16896;    // [32][132]
    const int tx = threadIdx.x, b0 = blockIdx.x*32;
    for (int idx = tx; idx < 32*128; idx += 256)
        Hs[(idx>>7)*132 + (idx&127)] = __float_as_uint(h0c[(b0+(idx>>7))*128 + (idx&127)]);
    const int lid = tx&31, wid = tx>>5, gid = lid>>2, tig = lid&3;
    const int jc = wid*16 + tig*2;
    float creg[2][2][4], ireg[2][2][4];
    #pragma unroll
    for (int mb = 0; mb < 2; mb++)
        #pragma unroll
        for (int nb = 0; nb < 2; nb++) {
            float2 c1 = *(const float2*)&c0c[(b0+mb*16+gid)*128 + jc + nb*8];
            float2 c2 = *(const float2*)&c0c[(b0+mb*16+gid+8)*128 + jc + nb*8];
            creg[mb][nb][0]=c1.x; creg[mb][nb][1]=c1.y; creg[mb][nb][2]=c2.x; creg[mb][nb][3]=c2.y;
        }
    for (int idx = tx; idx < 4096; idx += 256) {     // prefetch pass 0 -> buf 0
        int n = idx>>5, c = idx&31;
        cpa16(sptr(&Ws[n*132 + c*4]), &Whc[(size_t)n*128 + c*4]);
    }
    CPCOMMIT();
    __syncthreads();
    for (int t = 0; t < SS; t++) {
        #pragma unroll 1
        for (int p = 0; p < 4; p++) {
            const int pc = t*4 + p;
            CPWAIT(0);
            __syncthreads();
            if (pc < SS*4-1) {
                const int np = (pc+1)&3, nb2 = (pc+1)&1;
                for (int idx = tx; idx < 4096; idx += 256) {
                    int n = idx>>5, c = idx&31;
                    cpa16(sptr(&Ws[nb2*16896 + n*132 + c*4]),
                          &Whc[(size_t)(np*128+n)*128 + c*4]);
                }
                CPCOMMIT();
            }
            const unsigned* Wb = Ws + (pc&1)*16896;
            float acc[2][2][4];
            #pragma unroll
            for (int mb = 0; mb < 2; mb++)
                #pragma unroll
                for (int nb = 0; nb < 2; nb++) {
                    float2 g1 = *(const float2*)&g_Gc[(size_t)(t*BB+b0+mb*16+gid)*512 + p*128 + jc + nb*8];
                    float2 g2 = *(const float2*)&g_Gc[(size_t)(t*BB+b0+mb*16+gid+8)*512 + p*128 + jc + nb*8];
                    acc[mb][nb][0]=g1.x; acc[mb][nb][1]=g1.y; acc[mb][nb][2]=g2.x; acc[mb][nb][3]=g2.y;
                }
            #pragma unroll
            for (int k0 = 0; k0 < 128; k0 += 8) {
                unsigned a[2][4], bf[2][2];
                #pragma unroll
                for (int mb = 0; mb < 2; mb++) ldA(a[mb], Hs, mb*16, k0, 132, gid, tig);
                #pragma unroll
                for (int nb = 0; nb < 2; nb++) ldB(bf[nb], Wb, wid*16+nb*8, k0, 132, gid, tig);
                #pragma unroll
                for (int mb = 0; mb < 2; mb++)
                    #pragma unroll
                    for (int nb = 0; nb < 2; nb++) mma8(acc[mb][nb], a[mb], bf[nb]);
            }
            #pragma unroll
            for (int mb = 0; mb < 2; mb++)
                #pragma unroll
                for (int nb = 0; nb < 2; nb++)
                    #pragma unroll
                    for (int qq = 0; qq < 4; qq++) {
                        float v = acc[mb][nb][qq];
                        if (p == 0)      ireg[mb][nb][qq] = sigm(v);
                        else if (p == 1) creg[mb][nb][qq] = sigm(v)*creg[mb][nb][qq];
                        else if (p == 2) creg[mb][nb][qq] += ireg[mb][nb][qq]*tanhf(v);
                        else             ireg[mb][nb][qq] = sigm(v);   // o gate
                    }
        }
        __syncthreads();   // all Hs reads done
        #pragma unroll
        for (int mb = 0; mb < 2; mb++)
            #pragma unroll
            for (int nb = 0; nb < 2; nb++) {
                float hv[4];
                #pragma unroll
                for (int qq = 0; qq < 4; qq++)
                    hv[qq] = ireg[mb][nb][qq]*tanhf(creg[mb][nb][qq]);
                int r1 = mb*16 + gid, r2 = r1 + 8, col = jc + nb*8;
                Hs[r1*132 + col]   = __float_as_uint(hv[0]);
                Hs[r1*132 + col+1] = __float_as_uint(hv[1]);
                Hs[r2*132 + col]   = __float_as_uint(hv[2]);
                Hs[r2*132 + col+1] = __float_as_uint(hv[3]);
                if (t == SS-1) {
                    *(float2*)&g_hL[(b0+r1)*128 + col] = make_float2(hv[0],hv[1]);
                    *(float2*)&g_hL[(b0+r2)*128 + col] = make_float2(hv[2],hv[3]);
                }
            }
    }
}

// ======== K5: out = hL @ Wd^T + bd ========
__global__ __launch_bounds__(256) void k5(
    const float* __restrict__ Wd, const float* __restrict__ bd, float* __restrict__ out)
{
    extern __shared__ unsigned sm[];
    unsigned* Bs = sm;              // [128][132]
    unsigned* As = sm + 128*132;    // [64][132]
    const int tx = threadIdx.x;
    const int v0 = blockIdx.x*128, m0b = blockIdx.y*64;
    for (int idx = tx; idx < 128*32; idx += 256) {
        int n = idx>>5, c = idx&31;
        cpa16(sptr(&Bs[n*132 + c*4]), &Wd[(size_t)(v0+n)*128 + c*4]);
    }
    for (int idx = tx; idx < 64*32; idx += 256) {
        int m = idx>>5, c = idx&31;
        cpa16(sptr(&As[m*132 + c*4]), &g_hL[(m0b+m)*128 + c*4]);
    }
    CPCOMMIT(); CPWAIT(0);
    __syncthreads();
    const int lid = tx&31, wid = tx>>5, gid = lid>>2, tig = lid&3;
    const int wm = wid>>2, wn = wid&3;
    float acc[2][4][4];
    #pragma unroll
    for (int mb = 0; mb < 2; mb++)
        #pragma unroll
        for (int nb = 0; nb < 4; nb++)
            #pragma unroll
            for (int r = 0; r < 4; r++) acc[mb][nb][r] = 0.f;
    #pragma unroll
    for (int k0 = 0; k0 < 128; k0 += 8) {
        unsigned a[2][4], b[4][2];
        #pragma unroll
        for (int mb = 0; mb < 2; mb++) ldA(a[mb], As, wm*32+mb*16, k0, 132, gid, tig);
        #pragma unroll
        for (int nb = 0; nb < 4; nb++) ldB(b[nb], Bs, wn*32+nb*8, k0, 132, gid, tig);
        #pragma unroll
        for (int mb = 0; mb < 2; mb++)
            #pragma unroll
            for (int nb = 0; nb < 4; nb++) mma8(acc[mb][nb], a[mb], b[nb]);
    }
    #pragma unroll
    for (int mb = 0; mb < 2; mb++)
        #pragma unroll
        for (int nb = 0; nb < 4; nb++) {
            int row = m0b + wm*32 + mb*16 + gid;
            int col = v0 + wn*32 + nb*8 + tig*2;
            float2 bb = *(const float2*)&bd[col];
            *(float2*)&out[(size_t)row*VV + col] =
                make_float2(acc[mb][nb][0]+bb.x, acc[mb][nb][1]+bb.y);
            *(float2*)&out[(size_t)(row+8)*VV + col] =
                make_float2(acc[mb][nb][2]+bb.x, acc[mb][nb][3]+bb.y);
        }
}

extern "C" void kernel_launch(void* const* d_in, const int* in_sizes, int n_in,
                              void* d_out, int out_size) {
    const void*  x     = d_in[0];
    const float* h0f   = (const float*)d_in[1];
    const float* c0f   = (const float*)d_in[2];
    const float* h0b   = (const float*)d_in[3];
    const float* c0b   = (const float*)d_in[4];
    const float* h0c   = (const float*)d_in[5];
    const float* c0c   = (const float*)d_in[6];
    const float* emb   = (const float*)d_in[7];
    const float* Wih_f = (const float*)d_in[8];
    const float* Whh_f = (const float*)d_in[9];
    const float* bih_f = (const float*)d_in[10];
    const float* bhh_f = (const float*)d_in[11];
    const float* Wih_b = (const float*)d_in[12];
    const float* Whh_b = (const float*)d_in[13];
    const float* bih_b = (const float*)d_in[14];
    const float* bhh_b = (const float*)d_in[15];
    const float* Wih_c = (const float*)d_in[16];
    const float* Whh_c = (const float*)d_in[17];
    const float* bih_c = (const float*)d_in[18];
    const float* bhh_c = (const float*)d_in[19];
    const float* Wd    = (const float*)d_in[20];
    const float* bd    = (const float*)d_in[21];
    float* out = (float*)d_out;

    const int s2 = (17408*2 + 2*2176 + 2176 + 1024)*4;   // 169472
    const int s3 = (128*132*2)*4;                        // 135168
    const int s4 = (2*16896 + 32*132)*4;                 // 152064
    const int s5 = (128*132 + 64*132)*4;                 // 101376
    cudaFuncSetAttribute(k2f, cudaFuncAttributeMaxDynamicSharedMemorySize, s2);
    cudaFuncSetAttribute(k3,  cudaFuncAttributeMaxDynamicSharedMemorySize, s3);
    cudaFuncSetAttribute(k4,  cudaFuncAttributeMaxDynamicSharedMemorySize, s4);
    cudaFuncSetAttribute(k5,  cudaFuncAttributeMaxDynamicSharedMemorySize, s5);

    k2f<<<dim3(BB/32, 2), 256, s2>>>(x, emb,
        Wih_f, Whh_f, bih_f, bhh_f, h0f, c0f,
        Wih_b, Whh_b, bih_b, bhh_b, h0b, c0b);
    k3<<<dim3(SB/128, 4), 256, s3>>>(Wih_c, bih_c, bhh_c);
    k4<<<dim3(BB/32, 1), 256, s4>>>(Whh_c, h0c, c0c);
    k5<<<dim3(VV/128, BB/64), 256, s5>>>(Wd, bd, out);
}

// round 6
// speedup vs baseline: 4.0429x; 1.0559x over previous
#include <cuda_runtime.h>
#include <math.h>

#define SS 32
#define EE 64
#define VV 32000
#define BB 4096
#define SB (SS*BB)

__device__ float g_hf[(size_t)SB*EE];
__device__ float g_hb[(size_t)SB*EE];
__device__ float g_Gc[(size_t)SB*512];
__device__ float g_hL[BB*128];
// RNA-pre-rounded tf32 operand copies
__device__ unsigned r_emb[(size_t)VV*EE];
__device__ unsigned r_Wif[256*64], r_Whf[256*64], r_Wib[256*64], r_Whb[256*64];
__device__ unsigned r_Wc[512*128], r_Whc[512*128];
__device__ unsigned r_Wd[(size_t)VV*128];

__device__ __forceinline__ float sigm(float x){ return 1.0f/(1.0f+__expf(-x)); }
__device__ __forceinline__ unsigned rnd(float f){ return __float_as_uint(f) + 0x1000u; }
__device__ __forceinline__ unsigned sptr(const void* p){
    return (unsigned)__cvta_generic_to_shared(p);
}
__device__ __forceinline__ void cpa16(unsigned d, const void* s){
    asm volatile("cp.async.cg.shared.global [%0], [%1], 16;" :: "r"(d), "l"(s));
}
#define CPCOMMIT() asm volatile("cp.async.commit_group;")
#define CPWAIT(n)  asm volatile("cp.async.wait_group %0;" :: "n"(n))

__device__ __forceinline__ void mma8(float* c, const unsigned* a, const unsigned* b){
    asm volatile("mma.sync.aligned.m16n8k8.row.col.f32.tf32.tf32.f32 "
        "{%0,%1,%2,%3}, {%4,%5,%6,%7}, {%8,%9}, {%0,%1,%2,%3};"
        : "+f"(c[0]), "+f"(c[1]), "+f"(c[2]), "+f"(c[3])
        : "r"(a[0]), "r"(a[1]), "r"(a[2]), "r"(a[3]), "r"(b[0]), "r"(b[1]));
}
__device__ __forceinline__ void ldA(unsigned* a, const unsigned* S, int m0, int k0,
                                    int pad, int gid, int tig){
    a[0] = S[(m0+gid  )*pad + k0+tig  ];
    a[1] = S[(m0+gid+8)*pad + k0+tig  ];
    a[2] = S[(m0+gid  )*pad + k0+tig+4];
    a[3] = S[(m0+gid+8)*pad + k0+tig+4];
}
__device__ __forceinline__ void ldB(unsigned* b, const unsigned* S, int n0, int k0,
                                    int pad, int gid, int tig){
    b[0] = S[(n0+gid)*pad + k0+tig  ];
    b[1] = S[(n0+gid)*pad + k0+tig+4];
}

// ======== K0: RNA-round all tf32 operands once ========
__global__ void k0(const float* __restrict__ emb,
    const float* __restrict__ Wif, const float* __restrict__ Whf,
    const float* __restrict__ Wib, const float* __restrict__ Whb,
    const float* __restrict__ Wc,  const float* __restrict__ Whc,
    const float* __restrict__ Wd)
{
    int tid = blockIdx.x*256 + threadIdx.x, nt = gridDim.x*256;
    for (int i = tid; i < VV*EE; i += nt) r_emb[i] = rnd(emb[i]);
    for (int i = tid; i < 256*64; i += nt) {
        r_Wif[i] = rnd(Wif[i]); r_Whf[i] = rnd(Whf[i]);
        r_Wib[i] = rnd(Wib[i]); r_Whb[i] = rnd(Whb[i]);
    }
    for (int i = tid; i < 512*128; i += nt) { r_Wc[i] = rnd(Wc[i]); r_Whc[i] = rnd(Whc[i]); }
    for (int i = tid; i < VV*128; i += nt) r_Wd[i] = rnd(Wd[i]);
}

// ======== K2F: fused embed + input-gate GEMM + fwd/bwd LSTM recurrence ========
__global__ __launch_bounds__(256) void k2f(const void* __restrict__ xraw,
    const float* __restrict__ bif, const float* __restrict__ bhf,
    const float* __restrict__ h0f, const float* __restrict__ c0f,
    const float* __restrict__ bib, const float* __restrict__ bhb,
    const float* __restrict__ h0b, const float* __restrict__ c0b)
{
    extern __shared__ unsigned sm[];
    unsigned* Wi = sm;              // [256][68]
    unsigned* Wh = sm + 17408;      // [256][68]
    unsigned* As = sm + 34816;      // 2 x [32][68]
    unsigned* Hs = sm + 39168;      // [32][68]
    int*      Tk = (int*)(sm + 41344);
    __shared__ int s64;
    const int tx = threadIdx.x, dir = blockIdx.y, b0 = blockIdx.x*32;
    const unsigned* Wih = dir ? r_Wib : r_Wif;
    const unsigned* Whh = dir ? r_Whb : r_Whf;
    const float* bi  = dir ? bib : bif;
    const float* bh  = dir ? bhb : bhf;
    const float* h0  = dir ? h0b : h0f;
    const float* c0  = dir ? c0b : c0f;
    float* H = dir ? g_hb : g_hf;

    for (int idx = tx; idx < 256*16; idx += 256) {
        int n = idx>>4, c = idx&15;
        cpa16(sptr(&Wi[n*68 + c*4]), &Wih[n*64 + c*4]);
        cpa16(sptr(&Wh[n*68 + c*4]), &Whh[n*64 + c*4]);
    }
    CPCOMMIT();
    if (tx == 0) {
        const int* p = (const int*)xraw; int f = 1;
        for (int q = 0; q < 64; q++) if (p[2*q+1] != 0) { f = 0; break; }
        s64 = f;
    }
    __syncthreads();
    {
        const long long* x64 = (const long long*)xraw;
        const int* x32 = (const int*)xraw;
        const int is64 = s64;
        for (int idx = tx; idx < 1024; idx += 256) {
            int t = idx>>5, r = idx&31;
            int pos = dir ? (SS-1-t)*BB + b0 + r : t*BB + b0 + r;
            Tk[idx] = is64 ? (int)x64[pos] : x32[pos];
        }
    }
    for (int idx = tx; idx < 32*64; idx += 256)
        Hs[(idx>>6)*68 + (idx&63)] = rnd(h0[(b0+(idx>>6))*64 + (idx&63)]);
    __syncthreads();
    for (int idx = tx; idx < 32*16; idx += 256) {
        int r = idx>>4, c = idx&15;
        cpa16(sptr(&As[r*68 + c*4]), &r_emb[Tk[r]*64 + c*4]);
    }
    CPCOMMIT();

    const int lid = tx&31, wid = tx>>5, gid = lid>>2, tig = lid&3;
    const int jc = wid*8 + tig*2;
    float bA[4][2];
    #pragma unroll
    for (int g = 0; g < 4; g++) {
        bA[g][0] = bi[g*64+jc]   + bh[g*64+jc];
        bA[g][1] = bi[g*64+jc+1] + bh[g*64+jc+1];
    }
    float creg[2][4];
    #pragma unroll
    for (int mb = 0; mb < 2; mb++) {
        float2 c1 = *(const float2*)&c0[(b0+mb*16+gid)*64 + jc];
        float2 c2 = *(const float2*)&c0[(b0+mb*16+gid+8)*64 + jc];
        creg[mb][0]=c1.x; creg[mb][1]=c1.y; creg[mb][2]=c2.x; creg[mb][3]=c2.y;
    }
    for (int t = 0; t < SS; t++) {
        if (t < SS-1) {
            for (int idx = tx; idx < 32*16; idx += 256) {
                int r = idx>>4, c = idx&15;
                cpa16(sptr(&As[((t+1)&1)*2176 + r*68 + c*4]), &r_emb[Tk[(t+1)*32+r]*64 + c*4]);
            }
            CPCOMMIT(); CPWAIT(1);
        } else CPWAIT(0);
        __syncthreads();
        const unsigned* Ab = As + (t&1)*2176;
        float acc[2][4][4];
        #pragma unroll
        for (int mb = 0; mb < 2; mb++)
            #pragma unroll
            for (int g = 0; g < 4; g++) {
                acc[mb][g][0]=bA[g][0]; acc[mb][g][1]=bA[g][1];
                acc[mb][g][2]=bA[g][0]; acc[mb][g][3]=bA[g][1];
            }
        #pragma unroll
        for (int k0 = 0; k0 < 64; k0 += 8) {
            unsigned a[2][4], bf[4][2];
            #pragma unroll
            for (int mb = 0; mb < 2; mb++) ldA(a[mb], Ab, mb*16, k0, 68, gid, tig);
            #pragma unroll
            for (int g = 0; g < 4; g++) ldB(bf[g], Wi, g*64 + wid*8, k0, 68, gid, tig);
            #pragma unroll
            for (int mb = 0; mb < 2; mb++)
                #pragma unroll
                for (int g = 0; g < 4; g++) mma8(acc[mb][g], a[mb], bf[g]);
        }
        #pragma unroll
        for (int k0 = 0; k0 < 64; k0 += 8) {
            unsigned a[2][4], bf[4][2];
            #pragma unroll
            for (int mb = 0; mb < 2; mb++) ldA(a[mb], Hs, mb*16, k0, 68, gid, tig);
            #pragma unroll
            for (int g = 0; g < 4; g++) ldB(bf[g], Wh, g*64 + wid*8, k0, 68, gid, tig);
            #pragma unroll
            for (int mb = 0; mb < 2; mb++)
                #pragma unroll
                for (int g = 0; g < 4; g++) mma8(acc[mb][g], a[mb], bf[g]);
        }
        __syncthreads();
        #pragma unroll
        for (int mb = 0; mb < 2; mb++) {
            unsigned hu[4];
            #pragma unroll
            for (int q = 0; q < 4; q++) {
                float iv = sigm(acc[mb][0][q]);
                float fv = sigm(acc[mb][1][q]);
                float gv = tanhf(acc[mb][2][q]);
                float ov = sigm(acc[mb][3][q]);
                float c = fv*creg[mb][q] + iv*gv;
                hu[q] = rnd(ov*tanhf(c));
                creg[mb][q] = c;
            }
            int r1 = mb*16 + gid, r2 = r1 + 8;
            Hs[r1*68 + jc]   = hu[0];
            Hs[r1*68 + jc+1] = hu[1];
            Hs[r2*68 + jc]   = hu[2];
            Hs[r2*68 + jc+1] = hu[3];
            *(float2*)&H[(size_t)(t*BB + b0 + r1)*64 + jc] =
                make_float2(__uint_as_float(hu[0]), __uint_as_float(hu[1]));
            *(float2*)&H[(size_t)(t*BB + b0 + r2)*64 + jc] =
                make_float2(__uint_as_float(hu[2]), __uint_as_float(hu[3]));
        }
    }
}

// ======== K3: Gc = [hf|hb] @ Wih_c^T + biases. 128x128 tile, k-chunk pipeline ====
__global__ __launch_bounds__(256,2) void k3(
    const float* __restrict__ bic, const float* __restrict__ bhc)
{
    extern __shared__ unsigned sm[];
    unsigned* Ab = sm;            // 2 x [128][36]
    unsigned* Bb = sm + 2*4608;   // 2 x [128][36]
    const int tx = threadIdx.x, q = blockIdx.y, r0blk = blockIdx.x*128;
    for (int idx = tx; idx < 1024; idx += 256) {
        int r = idx>>3, f = idx&7;
        cpa16(sptr(&Ab[r*36 + f*4]), &g_hf[(size_t)(r0blk+r)*64 + f*4]);
        cpa16(sptr(&Bb[r*36 + f*4]), &r_Wc[(q*128+r)*128 + f*4]);
    }
    CPCOMMIT();
    const int lid = tx&31, wid = tx>>5, gid = lid>>2, tig = lid&3;
    const int wm = wid&1, wn = wid>>1;
    float acc[4][4][4];
    #pragma unroll
    for (int nb = 0; nb < 4; nb++) {
        int col = q*128 + wn*32 + nb*8 + tig*2;
        float b0v = bic[col]+bhc[col], b1v = bic[col+1]+bhc[col+1];
        #pragma unroll
        for (int mb = 0; mb < 4; mb++) {
            acc[mb][nb][0]=b0v; acc[mb][nb][1]=b1v; acc[mb][nb][2]=b0v; acc[mb][nb][3]=b1v;
        }
    }
    #pragma unroll 1
    for (int c = 0; c < 4; c++) {
        CPWAIT(0); __syncthreads();
        if (c < 3) {
            int cc = c+1, nb2 = cc&1, koff = (cc&1)*32;
            const float* Asrc = (cc < 2) ? g_hf : g_hb;
            for (int idx = tx; idx < 1024; idx += 256) {
                int r = idx>>3, f = idx&7;
                cpa16(sptr(&Ab[nb2*4608 + r*36 + f*4]),
                      &Asrc[(size_t)(r0blk+r)*64 + koff + f*4]);
                cpa16(sptr(&Bb[nb2*4608 + r*36 + f*4]),
                      &r_Wc[(q*128+r)*128 + cc*32 + f*4]);
            }
            CPCOMMIT();
        }
        const unsigned* Au = Ab + (c&1)*4608;
        const unsigned* Bu = Bb + (c&1)*4608;
        #pragma unroll
        for (int k0 = 0; k0 < 32; k0 += 8) {
            unsigned a[4][4], b[4][2];
            #pragma unroll
            for (int mb = 0; mb < 4; mb++) ldA(a[mb], Au, wm*64+mb*16, k0, 36, gid, tig);
            #pragma unroll
            for (int nb = 0; nb < 4; nb++) ldB(b[nb], Bu, wn*32+nb*8, k0, 36, gid, tig);
            #pragma unroll
            for (int mb = 0; mb < 4; mb++)
                #pragma unroll
                for (int nb = 0; nb < 4; nb++) mma8(acc[mb][nb], a[mb], b[nb]);
        }
    }
    #pragma unroll
    for (int mb = 0; mb < 4; mb++)
        #pragma unroll
        for (int nb = 0; nb < 4; nb++) {
            int row = r0blk + wm*64 + mb*16 + gid;
            int col = q*128 + wn*32 + nb*8 + tig*2;
            *(float2*)&g_Gc[(size_t)row*512 + col]     = make_float2(acc[mb][nb][0],acc[mb][nb][1]);
            *(float2*)&g_Gc[(size_t)(row+8)*512 + col] = make_float2(acc[mb][nb][2],acc[mb][nb][3]);
        }
}

// ======== K4: combiner recurrence, weight+gate double-buffered streaming ========
__global__ __launch_bounds__(256) void k4(
    const float* __restrict__ h0c, const float* __restrict__ c0c)
{
    extern __shared__ unsigned sm[];
    unsigned* Ws = sm;                  // 2 x [128][132]
    unsigned* Hs = sm + 33792;          // [32][132]
    unsigned* Gu = sm + 38016;          // 2 x [32][132]
    float* Gf = (float*)Gu;
    const int tx = threadIdx.x, b0 = blockIdx.x*32;
    for (int idx = tx; idx < 32*128; idx += 256)
        Hs[(idx>>7)*132 + (idx&127)] = rnd(h0c[(b0+(idx>>7))*128 + (idx&127)]);
    const int lid = tx&31, wid = tx>>5, gid = lid>>2, tig = lid&3;
    const int jc = wid*16 + tig*2;
    float creg[2][2][4], ireg[2][2][4];
    #pragma unroll
    for (int mb = 0; mb < 2; mb++)
        #pragma unroll
        for (int nb = 0; nb < 2; nb++) {
            float2 c1 = *(const float2*)&c0c[(b0+mb*16+gid)*128 + jc + nb*8];
            float2 c2 = *(const float2*)&c0c[(b0+mb*16+gid+8)*128 + jc + nb*8];
            creg[mb][nb][0]=c1.x; creg[mb][nb][1]=c1.y; creg[mb][nb][2]=c2.x; creg[mb][nb][3]=c2.y;
        }
    for (int idx = tx; idx < 4096; idx += 256) {
        int n = idx>>5, c = idx&31;
        cpa16(sptr(&Ws[n*132 + c*4]), &r_Whc[n*128 + c*4]);
    }
    for (int idx = tx; idx < 1024; idx += 256) {
        int r = idx>>5, f = idx&31;
        cpa16(sptr(&Gu[r*132 + f*4]), &g_Gc[(size_t)(b0+r)*512 + f*4]);
    }
    CPCOMMIT();
    __syncthreads();
    #pragma unroll 1
    for (int pc = 0; pc < SS*4; pc++) {
        const int t = pc>>2, p = pc&3, buf = pc&1;
        CPWAIT(0);
        __syncthreads();
        if (pc < SS*4-1) {
            const int np = (pc+1)&3, nt2 = (pc+1)>>2, nb2 = (pc+1)&1;
            for (int idx = tx; idx < 4096; idx += 256) {
                int n = idx>>5, c = idx&31;
                cpa16(sptr(&Ws[nb2*16896 + n*132 + c*4]), &r_Whc[(np*128+n)*128 + c*4]);
            }
            for (int idx = tx; idx < 1024; idx += 256) {
                int r = idx>>5, f = idx&31;
                cpa16(sptr(&Gu[nb2*4224 + r*132 + f*4]),
                      &g_Gc[(size_t)(nt2*BB + b0 + r)*512 + np*128 + f*4]);
            }
            CPCOMMIT();
        }
        const unsigned* Wb = Ws + buf*16896;
        const float* Gb = Gf + buf*4224;
        float acc[2][2][4];
        #pragma unroll
        for (int mb = 0; mb < 2; mb++)
            #pragma unroll
            for (int nb = 0; nb < 2; nb++) {
                float2 g1 = *(const float2*)&Gb[(mb*16+gid)*132 + jc + nb*8];
                float2 g2 = *(const float2*)&Gb[(mb*16+gid+8)*132 + jc + nb*8];
                acc[mb][nb][0]=g1.x; acc[mb][nb][1]=g1.y; acc[mb][nb][2]=g2.x; acc[mb][nb][3]=g2.y;
            }
        #pragma unroll
        for (int k0 = 0; k0 < 128; k0 += 8) {
            unsigned a[2][4], bf[2][2];
            #pragma unroll
            for (int mb = 0; mb < 2; mb++) ldA(a[mb], Hs, mb*16, k0, 132, gid, tig);
            #pragma unroll
            for (int nb = 0; nb < 2; nb++) ldB(bf[nb], Wb, wid*16+nb*8, k0, 132, gid, tig);
            #pragma unroll
            for (int mb = 0; mb < 2; mb++)
                #pragma unroll
                for (int nb = 0; nb < 2; nb++) mma8(acc[mb][nb], a[mb], bf[nb]);
        }
        #pragma unroll
        for (int mb = 0; mb < 2; mb++)
            #pragma unroll
            for (int nb = 0; nb < 2; nb++)
                #pragma unroll
                for (int qq = 0; qq < 4; qq++) {
                    float v = acc[mb][nb][qq];
                    if (p == 0)      ireg[mb][nb][qq] = sigm(v);
                    else if (p == 1) creg[mb][nb][qq] = sigm(v)*creg[mb][nb][qq];
                    else if (p == 2) creg[mb][nb][qq] += ireg[mb][nb][qq]*tanhf(v);
                    else             ireg[mb][nb][qq] = sigm(v);
                }
        if (p == 3) {
            __syncthreads();
            #pragma unroll
            for (int mb = 0; mb < 2; mb++)
                #pragma unroll
                for (int nb = 0; nb < 2; nb++) {
                    unsigned hu[4];
                    #pragma unroll
                    for (int qq = 0; qq < 4; qq++)
                        hu[qq] = rnd(ireg[mb][nb][qq]*tanhf(creg[mb][nb][qq]));
                    int r1 = mb*16 + gid, r2 = r1 + 8, col = jc + nb*8;
                    Hs[r1*132 + col]   = hu[0];
                    Hs[r1*132 + col+1] = hu[1];
                    Hs[r2*132 + col]   = hu[2];
                    Hs[r2*132 + col+1] = hu[3];
                    if (t == SS-1) {
                        *(float2*)&g_hL[(b0+r1)*128 + col] =
                            make_float2(__uint_as_float(hu[0]), __uint_as_float(hu[1]));
                        *(float2*)&g_hL[(b0+r2)*128 + col] =
                            make_float2(__uint_as_float(hu[2]), __uint_as_float(hu[3]));
                    }
                }
        }
    }
}

// ======== K5: out = hL @ Wd^T + bd. 128x128 tile, k-chunk pipeline ========
__global__ __launch_bounds__(256,2) void k5(
    const float* __restrict__ bd, float* __restrict__ out)
{
    extern __shared__ unsigned sm[];
    unsigned* As = sm;            // [128][132]
    unsigned* Bb = sm + 16896;    // 2 x [128][36]
    const int tx = threadIdx.x;
    const int v0 = blockIdx.x*128, m0b = blockIdx.y*128;
    for (int idx = tx; idx < 4096; idx += 256) {
        int m = idx>>5, f = idx&31;
        cpa16(sptr(&As[m*132 + f*4]), &g_hL[(m0b+m)*128 + f*4]);
    }
    for (int idx = tx; idx < 1024; idx += 256) {
        int n = idx>>3, f = idx&7;
        cpa16(sptr(&Bb[n*36 + f*4]), &r_Wd[(size_t)(v0+n)*128 + f*4]);
    }
    CPCOMMIT();
    const int lid = tx&31, wid = tx>>5, gid = lid>>2, tig = lid&3;
    const int wm = wid&1, wn = wid>>1;
    float acc[4][4][4];
    #pragma unroll
    for (int mb = 0; mb < 4; mb++)
        #pragma unroll
        for (int nb = 0; nb < 4; nb++)
            #pragma unroll
            for (int r = 0; r < 4; r++) acc[mb][nb][r] = 0.f;
    #pragma unroll 1
    for (int c = 0; c < 4; c++) {
        CPWAIT(0); __syncthreads();
        if (c < 3) {
            int nb2 = (c+1)&1;
            for (int idx = tx; idx < 1024; idx += 256) {
                int n = idx>>3, f = idx&7;
                cpa16(sptr(&Bb[nb2*4608 + n*36 + f*4]),
                      &r_Wd[(size_t)(v0+n)*128 + (c+1)*32 + f*4]);
            }
            CPCOMMIT();
        }
        const unsigned* Bu = Bb + (c&1)*4608;
        #pragma unroll
        for (int k0 = 0; k0 < 32; k0 += 8) {
            unsigned a[4][4], b[4][2];
            #pragma unroll
            for (int mb = 0; mb < 4; mb++) ldA(a[mb], As, wm*64+mb*16, c*32+k0, 132, gid, tig);
            #pragma unroll
            for (int nb = 0; nb < 4; nb++) ldB(b[nb], Bu, wn*32+nb*8, k0, 36, gid, tig);
            #pragma unroll
            for (int mb = 0; mb < 4; mb++)
                #pragma unroll
                for (int nb = 0; nb < 4; nb++) mma8(acc[mb][nb], a[mb], b[nb]);
        }
    }
    #pragma unroll
    for (int mb = 0; mb < 4; mb++)
        #pragma unroll
        for (int nb = 0; nb < 4; nb++) {
            int row = m0b + wm*64 + mb*16 + gid;
            int col = v0 + wn*32 + nb*8 + tig*2;
            float2 bb = *(const float2*)&bd[col];
            *(float2*)&out[(size_t)row*VV + col] =
                make_float2(acc[mb][nb][0]+bb.x, acc[mb][nb][1]+bb.y);
            *(float2*)&out[(size_t)(row+8)*VV + col] =
                make_float2(acc[mb][nb][2]+bb.x, acc[mb][nb][3]+bb.y);
        }
}

extern "C" void kernel_launch(void* const* d_in, const int* in_sizes, int n_in,
                              void* d_out, int out_size) {
    const void*  x     = d_in[0];
    const float* h0f   = (const float*)d_in[1];
    const float* c0f   = (const float*)d_in[2];
    const float* h0b   = (const float*)d_in[3];
    const float* c0b   = (const float*)d_in[4];
    const float* h0c   = (const float*)d_in[5];
    const float* c0c   = (const float*)d_in[6];
    const float* emb   = (const float*)d_in[7];
    const float* Wih_f = (const float*)d_in[8];
    const float* Whh_f = (const float*)d_in[9];
    const float* bih_f = (const float*)d_in[10];
    const float* bhh_f = (const float*)d_in[11];
    const float* Wih_b = (const float*)d_in[12];
    const float* Whh_b = (const float*)d_in[13];
    const float* bih_b = (const float*)d_in[14];
    const float* bhh_b = (const float*)d_in[15];
    const float* Wih_c = (const float*)d_in[16];
    const float* Whh_c = (const float*)d_in[17];
    const float* bih_c = (const float*)d_in[18];
    const float* bhh_c = (const float*)d_in[19];
    const float* Wd    = (const float*)d_in[20];
    const float* bd    = (const float*)d_in[21];
    float* out = (float*)d_out;

    const int s2 = (17408*2 + 2*2176 + 2176 + 1024)*4;   // 169472
    const int s3 = (4*4608)*4;                           // 73728
    const int s4 = (2*16896 + 4224 + 2*4224)*4;          // 185856
    const int s5 = (16896 + 2*4608)*4;                   // 104448
    cudaFuncSetAttribute(k2f, cudaFuncAttributeMaxDynamicSharedMemorySize, s2);
    cudaFuncSetAttribute(k3,  cudaFuncAttributeMaxDynamicSharedMemorySize, s3);
    cudaFuncSetAttribute(k4,  cudaFuncAttributeMaxDynamicSharedMemorySize, s4);
    cudaFuncSetAttribute(k5,  cudaFuncAttributeMaxDynamicSharedMemorySize, s5);

    k0<<<1024, 256>>>(emb, Wih_f, Whh_f, Wih_b, Whh_b, Wih_c, Whh_c, Wd);
    k2f<<<dim3(BB/32, 2), 256, s2>>>(x, bih_f, bhh_f, h0f, c0f, bih_b, bhh_b, h0b, c0b);
    k3<<<dim3(SB/128, 4), 256, s3>>>(bih_c, bhh_c);
    k4<<<dim3(BB/32, 1), 256, s4>>>(h0c, c0c);
    k5<<<dim3(VV/128, BB/128), 256, s5>>>(bd, out);
}